// round 6
// baseline (speedup 1.0000x reference)
#include <cuda_runtime.h>
#include <cuda_bf16.h>
#include <math.h>

#define BN 64
#define CN 64
#define LN 8192
#define CPB 16                        // reducer CTAs per batch
#define CHUNK4 ((CN * LN / CPB) / 4)  // 8192 float4 per CTA (4 whole L-rows)
#define REDUCE_CTAS (BN * CPB)        // 1024
#define TAIL_CTAS 513                 // 512 for idxes (int4/thread) + 1 for zero_pos
#define EPSV 1.1920928955078125e-7f   // np.float32 eps

__device__ float2   g_partial[BN * CPB];  // per-CTA (sum, sumsq), fixed slot
__device__ float2   g_stats[BN];          // (mean, 1/(std+eps))
__device__ unsigned g_ticket[BN];         // monotonic across graph replays

// ---------------------------------------------------------------------------
// Kernel A: masked reduce -> partials; LAST arriver per batch (wait-free)
// combines partials in fixed order and writes stats. Tail CTAs copy
// idxes/zero_pos concurrently (hidden under the prefix read).
// ---------------------------------------------------------------------------
__global__ __launch_bounds__(256) void reduce_stats_tail_kernel(
    const float* __restrict__ data, const int* __restrict__ idxes,
    const int* __restrict__ zero_pos, float* __restrict__ out,
    long long out_size) {
    const int bid = blockIdx.x;
    const long long main_elems = (long long)BN * CN * LN;

    // ---- tail CTAs
    if (bid >= REDUCE_CTAS) {
        const int t = bid - REDUCE_CTAS;
        if (t < 512) {
            const int i = t * 256 + threadIdx.x;  // int4 index into idxes
            const long long base = main_elems + (long long)i * 4;
            if (base + 3 < out_size) {
                int4 v = reinterpret_cast<const int4*>(idxes)[i];
                float4 f = make_float4((float)v.x, (float)v.y, (float)v.z, (float)v.w);
                __stcs(reinterpret_cast<float4*>(out + base), f);
            }
        } else {
            const int i = threadIdx.x;
            const long long pos = main_elems + (long long)BN * LN + i;
            if (i < BN && pos < out_size)
                out[pos] = (float)zero_pos[i];
        }
        return;
    }

    // ---- reducer CTAs
    const int b = bid >> 4;          // batch
    const int j = bid & (CPB - 1);   // chunk within batch
    const int zp = zero_pos[b];

    const float4* base =
        reinterpret_cast<const float4*>(data + (size_t)b * CN * LN) + (size_t)j * CHUNK4;

    float s = 0.f, ss = 0.f;
    #pragma unroll 4
    for (int i = threadIdx.x; i < CHUNK4; i += 256) {
        const int l = (i * 4) & (LN - 1);  // chunk = whole rows; float4 stays in-row
        if (l < zp) {
            float4 v = base[i];
            if (l + 3 < zp) {
                s  += v.x + v.y + v.z + v.w;
                ss += v.x * v.x + v.y * v.y + v.z * v.z + v.w * v.w;
            } else {
                if (l + 0 < zp) { s += v.x; ss += v.x * v.x; }
                if (l + 1 < zp) { s += v.y; ss += v.y * v.y; }
                if (l + 2 < zp) { s += v.z; ss += v.z * v.z; }
            }
        }
    }

    // Block reduction (warp shuffles + 8-slot shared)
    __shared__ float sh_s[8], sh_ss[8];
    const int lane = threadIdx.x & 31;
    const int warp = threadIdx.x >> 5;
    #pragma unroll
    for (int off = 16; off > 0; off >>= 1) {
        s  += __shfl_down_sync(0xffffffffu, s, off);
        ss += __shfl_down_sync(0xffffffffu, ss, off);
    }
    if (lane == 0) { sh_s[warp] = s; sh_ss[warp] = ss; }
    __syncthreads();

    if (threadIdx.x == 0) {
        float ts = 0.f, tss = 0.f;
        #pragma unroll
        for (int w = 0; w < 8; w++) { ts += sh_s[w]; tss += sh_ss[w]; }
        g_partial[bid] = make_float2(ts, tss);
        __threadfence();  // publish partial before arriving
        const unsigned old = atomicAdd(&g_ticket[b], 1u);
        if ((old & (CPB - 1)) == CPB - 1) {
            // Last arriver: all 15 siblings have published. Combine in FIXED
            // order (deterministic regardless of arrival order). Nobody waits.
            __threadfence();
            double ds = 0.0, dss = 0.0;
            #pragma unroll
            for (int k = 0; k < CPB; k++) {
                volatile float* p = (volatile float*)&g_partial[b * CPB + k];
                ds  += (double)p[0];
                dss += (double)p[1];
            }
            const double cnt  = (double)CN * (double)zp;
            const double mean = ds / cnt;
            const double var  = (dss - cnt * mean * mean) / (cnt - 1.0);
            const float  stdv = (float)sqrt(var > 0.0 ? var : 0.0);
            g_stats[b] = make_float2((float)mean, 1.0f / (stdv + EPSV));
            __threadfence();
        }
    }
}

// ---------------------------------------------------------------------------
// Kernel B: streaming normalize, one float4 per thread.
// ---------------------------------------------------------------------------
__global__ __launch_bounds__(256) void norm_kernel(
    const float* __restrict__ data, float* __restrict__ out) {
    const size_t i = (size_t)blockIdx.x * 256 + threadIdx.x;  // float4 index
    const int b = (int)(i >> 17);  // / (CN*LN/4) = 131072
    const float2 st = __ldcg(&g_stats[b]);
    float4 v = __ldcs(reinterpret_cast<const float4*>(data) + i);
    v.x = (v.x - st.x) * st.y;
    v.y = (v.y - st.x) * st.y;
    v.z = (v.z - st.x) * st.y;
    v.w = (v.w - st.x) * st.y;
    __stcs(reinterpret_cast<float4*>(out) + i, v);
}

extern "C" void kernel_launch(void* const* d_in, const int* in_sizes, int n_in,
                              void* d_out, int out_size) {
    const float* data     = (const float*)d_in[0];
    const int*   idxes    = (const int*)d_in[1];
    const int*   zero_pos = (const int*)d_in[2];
    float*       out      = (float*)d_out;

    const long long main_elems = (long long)BN * CN * LN;
    const bool has_tail = (long long)out_size > main_elems;
    const unsigned gridA = REDUCE_CTAS + (has_tail ? TAIL_CTAS : 0);

    reduce_stats_tail_kernel<<<gridA, 256>>>(data, idxes, zero_pos, out,
                                             (long long)out_size);

    const size_t n4 = (size_t)BN * CN * LN / 4;
    norm_kernel<<<(unsigned)(n4 / 256), 256>>>(data, out);
}

// round 7
// speedup vs baseline: 1.4307x; 1.4307x over previous
#include <cuda_runtime.h>
#include <cuda_bf16.h>
#include <math.h>

#define BN 64
#define CN 64
#define LN 8192
#define CPB 16                        // reducer CTAs per batch
#define CHUNK4 ((CN * LN / CPB) / 4)  // 8192 float4 per CTA (4 whole L-rows)
#define REDUCE_CTAS (BN * CPB)        // 1024
#define TAIL_CTAS 513                 // 512 for idxes (int4/thread) + 1 for zero_pos
#define EPSV 1.1920928955078125e-7f   // np.float32 eps

#define NB4 1024                      // float4 per norm CTA (4 per thread)
#define NORM_CTAS (BN * CN * LN / 4 / NB4)  // 8192

__device__ float2   g_partial[BN * CPB];  // per-CTA (sum, sumsq), fixed slot
__device__ float2   g_stats[BN];          // (mean, 1/(std+eps))
__device__ unsigned g_ticket[BN];         // monotonic across graph replays

// ---------------------------------------------------------------------------
// Kernel A: masked reduce -> partials; LAST arriver per batch (wait-free)
// combines partials in fixed order and writes stats. Tail CTAs copy
// idxes/zero_pos concurrently (hidden under the prefix read).
// ---------------------------------------------------------------------------
__global__ __launch_bounds__(256) void reduce_stats_tail_kernel(
    const float* __restrict__ data, const int* __restrict__ idxes,
    const int* __restrict__ zero_pos, float* __restrict__ out,
    long long out_size) {
    const int bid = blockIdx.x;
    const long long main_elems = (long long)BN * CN * LN;

    // ---- tail CTAs
    if (bid >= REDUCE_CTAS) {
        const int t = bid - REDUCE_CTAS;
        if (t < 512) {
            const int i = t * 256 + threadIdx.x;  // int4 index into idxes
            const long long base = main_elems + (long long)i * 4;
            if (base + 3 < out_size) {
                int4 v = reinterpret_cast<const int4*>(idxes)[i];
                reinterpret_cast<float4*>(out + base)[0] =
                    make_float4((float)v.x, (float)v.y, (float)v.z, (float)v.w);
            }
        } else {
            const int i = threadIdx.x;
            const long long pos = main_elems + (long long)BN * LN + i;
            if (i < BN && pos < out_size)
                out[pos] = (float)zero_pos[i];
        }
        return;
    }

    // ---- reducer CTAs
    const int b = bid >> 4;          // batch
    const int j = bid & (CPB - 1);   // chunk within batch
    const int zp = zero_pos[b];

    const float4* base =
        reinterpret_cast<const float4*>(data + (size_t)b * CN * LN) + (size_t)j * CHUNK4;

    float s = 0.f, ss = 0.f;
    #pragma unroll 4
    for (int i = threadIdx.x; i < CHUNK4; i += 256) {
        const int l = (i * 4) & (LN - 1);  // chunk = whole rows; float4 stays in-row
        if (l < zp) {
            float4 v = base[i];
            if (l + 3 < zp) {
                s  += v.x + v.y + v.z + v.w;
                ss += v.x * v.x + v.y * v.y + v.z * v.z + v.w * v.w;
            } else {
                if (l + 0 < zp) { s += v.x; ss += v.x * v.x; }
                if (l + 1 < zp) { s += v.y; ss += v.y * v.y; }
                if (l + 2 < zp) { s += v.z; ss += v.z * v.z; }
            }
        }
    }

    // Block reduction (warp shuffles + 8-slot shared)
    __shared__ float sh_s[8], sh_ss[8];
    const int lane = threadIdx.x & 31;
    const int warp = threadIdx.x >> 5;
    #pragma unroll
    for (int off = 16; off > 0; off >>= 1) {
        s  += __shfl_down_sync(0xffffffffu, s, off);
        ss += __shfl_down_sync(0xffffffffu, ss, off);
    }
    if (lane == 0) { sh_s[warp] = s; sh_ss[warp] = ss; }
    __syncthreads();

    if (threadIdx.x == 0) {
        float ts = 0.f, tss = 0.f;
        #pragma unroll
        for (int w = 0; w < 8; w++) { ts += sh_s[w]; tss += sh_ss[w]; }
        g_partial[bid] = make_float2(ts, tss);
        __threadfence();  // publish partial before arriving
        const unsigned old = atomicAdd(&g_ticket[b], 1u);
        if ((old & (CPB - 1)) == CPB - 1) {
            // Last arriver: all 15 siblings have published. Combine in FIXED
            // order (deterministic regardless of arrival order). Nobody waits.
            __threadfence();
            double ds = 0.0, dss = 0.0;
            #pragma unroll
            for (int k = 0; k < CPB; k++) {
                volatile float* p = (volatile float*)&g_partial[b * CPB + k];
                ds  += (double)p[0];
                dss += (double)p[1];
            }
            const double cnt  = (double)CN * (double)zp;
            const double mean = ds / cnt;
            const double var  = (dss - cnt * mean * mean) / (cnt - 1.0);
            const float  stdv = (float)sqrt(var > 0.0 ? var : 0.0);
            g_stats[b] = make_float2((float)mean, 1.0f / (stdv + EPSV));
            __threadfence();
        }
    }
}

// ---------------------------------------------------------------------------
// Kernel B: streaming normalize. 4 float4 per thread, loads front-batched
// (MLP=4); stats fetched once per CTA through shared memory.
// ---------------------------------------------------------------------------
__global__ __launch_bounds__(256) void norm_kernel(
    const float* __restrict__ data, float* __restrict__ out) {
    __shared__ float2 sh_st;
    const size_t base = (size_t)blockIdx.x * NB4;  // float4 index of CTA start
    if (threadIdx.x == 0)
        sh_st = g_stats[blockIdx.x >> 7];  // NB4*128 = 131072 float4 per batch
    __syncthreads();
    const float mean = sh_st.x, rstd = sh_st.y;

    const float4* in4 = reinterpret_cast<const float4*>(data) + base + threadIdx.x;
    float4*       o4  = reinterpret_cast<float4*>(out)        + base + threadIdx.x;

    float4 v0 = in4[0];
    float4 v1 = in4[256];
    float4 v2 = in4[512];
    float4 v3 = in4[768];

    v0.x = (v0.x - mean) * rstd; v0.y = (v0.y - mean) * rstd;
    v0.z = (v0.z - mean) * rstd; v0.w = (v0.w - mean) * rstd;
    v1.x = (v1.x - mean) * rstd; v1.y = (v1.y - mean) * rstd;
    v1.z = (v1.z - mean) * rstd; v1.w = (v1.w - mean) * rstd;
    v2.x = (v2.x - mean) * rstd; v2.y = (v2.y - mean) * rstd;
    v2.z = (v2.z - mean) * rstd; v2.w = (v2.w - mean) * rstd;
    v3.x = (v3.x - mean) * rstd; v3.y = (v3.y - mean) * rstd;
    v3.z = (v3.z - mean) * rstd; v3.w = (v3.w - mean) * rstd;

    o4[0]   = v0;
    o4[256] = v1;
    o4[512] = v2;
    o4[768] = v3;
}

extern "C" void kernel_launch(void* const* d_in, const int* in_sizes, int n_in,
                              void* d_out, int out_size) {
    const float* data     = (const float*)d_in[0];
    const int*   idxes    = (const int*)d_in[1];
    const int*   zero_pos = (const int*)d_in[2];
    float*       out      = (float*)d_out;

    const long long main_elems = (long long)BN * CN * LN;
    const bool has_tail = (long long)out_size > main_elems;
    const unsigned gridA = REDUCE_CTAS + (has_tail ? TAIL_CTAS : 0);

    reduce_stats_tail_kernel<<<gridA, 256>>>(data, idxes, zero_pos, out,
                                             (long long)out_size);
    norm_kernel<<<NORM_CTAS, 256>>>(data, out);
}

// round 9
// speedup vs baseline: 1.5712x; 1.0982x over previous
#include <cuda_runtime.h>
#include <cuda_bf16.h>
#include <math.h>

#define BN 64
#define CN 64
#define LN 8192
#define CPB 16                        // reducer CTAs per batch (4 rows each)
#define REDUCE_CTAS (BN * CPB)        // 1024
#define TAIL_CTAS 513                 // 512 for idxes (int4/thread) + 1 for zero_pos
#define EPSV 1.1920928955078125e-7f   // np.float32 eps
#define LN4 (LN / 4)                  // 2048 float4 per row

#define NB4 1024                      // float4 per norm CTA (4 per thread)
#define NORM_CTAS (BN * CN * LN / 4 / NB4)  // 8192

__device__ float2   g_partial[BN * CPB];  // per-CTA (sum, sumsq), fixed slot
__device__ float2   g_stats[BN];          // (mean, 1/(std+eps))
__device__ unsigned g_ticket[BN];         // monotonic across graph replays

// ---------------------------------------------------------------------------
// Kernel A: dense prefix reduce (4 rows/CTA, unconditional loads, MLP>=4);
// last arriver per batch (wait-free) combines partials in fixed order.
// Tail CTAs copy idxes/zero_pos concurrently.
// ---------------------------------------------------------------------------
__global__ __launch_bounds__(256) void reduce_stats_tail_kernel(
    const float* __restrict__ data, const int* __restrict__ idxes,
    const int* __restrict__ zero_pos, float* __restrict__ out,
    long long out_size) {
    const int bid = blockIdx.x;
    const long long main_elems = (long long)BN * CN * LN;

    // ---- tail CTAs (concurrent with the reduce)
    if (bid >= REDUCE_CTAS) {
        const int t = bid - REDUCE_CTAS;
        if (t < 512) {
            const int i = t * 256 + threadIdx.x;  // int4 index into idxes
            const long long base = main_elems + (long long)i * 4;
            if (base + 3 < out_size) {
                int4 v = reinterpret_cast<const int4*>(idxes)[i];
                reinterpret_cast<float4*>(out + base)[0] =
                    make_float4((float)v.x, (float)v.y, (float)v.z, (float)v.w);
            }
        } else {
            const int i = threadIdx.x;
            const long long pos = main_elems + (long long)BN * LN + i;
            if (i < BN && pos < out_size)
                out[pos] = (float)zero_pos[i];
        }
        return;
    }

    // ---- reducer CTAs: rows [j*4, j*4+4) of batch b
    const int b = bid >> 4;
    const int j = bid & (CPB - 1);
    const int zp = zero_pos[b];
    const int nfull = zp >> 2;   // float4 fully inside the prefix
    const int rem   = zp & 3;    // leftover elements in the boundary float4

    const float4* r0 = reinterpret_cast<const float4*>(
        data + (size_t)b * CN * LN + (size_t)(j * 4 + 0) * LN);
    const float4* r1 = r0 + LN4;
    const float4* r2 = r1 + LN4;
    const float4* r3 = r2 + LN4;

    float s0 = 0.f, s1 = 0.f, s2 = 0.f, s3 = 0.f;
    float q0 = 0.f, q1 = 0.f, q2 = 0.f, q3 = 0.f;

    // Dense main loop: 4 independent unconditional loads per iteration.
    #pragma unroll 2
    for (int i = threadIdx.x; i < nfull; i += 256) {
        float4 v0 = r0[i];
        float4 v1 = r1[i];
        float4 v2 = r2[i];
        float4 v3 = r3[i];
        s0 += (v0.x + v0.y) + (v0.z + v0.w);
        q0 += v0.x * v0.x + v0.y * v0.y + v0.z * v0.z + v0.w * v0.w;
        s1 += (v1.x + v1.y) + (v1.z + v1.w);
        q1 += v1.x * v1.x + v1.y * v1.y + v1.z * v1.z + v1.w * v1.w;
        s2 += (v2.x + v2.y) + (v2.z + v2.w);
        q2 += v2.x * v2.x + v2.y * v2.y + v2.z * v2.z + v2.w * v2.w;
        s3 += (v3.x + v3.y) + (v3.z + v3.w);
        q3 += v3.x * v3.x + v3.y * v3.y + v3.z * v3.z + v3.w * v3.w;
    }
    float s = (s0 + s1) + (s2 + s3);
    float ss = (q0 + q1) + (q2 + q3);

    // Boundary float4 (rem in 1..3): 4 threads, one row each.
    if (rem != 0 && threadIdx.x < 4) {
        const float* rowp = reinterpret_cast<const float*>(r0) +
                            (size_t)threadIdx.x * LN + (size_t)nfull * 4;
        #pragma unroll 3
        for (int e = 0; e < 3; e++) {
            if (e < rem) {
                float x = rowp[e];
                s += x;
                ss += x * x;
            }
        }
    }

    // Block reduction (warp shuffles + 8-slot shared)
    __shared__ float sh_s[8], sh_ss[8];
    const int lane = threadIdx.x & 31;
    const int warp = threadIdx.x >> 5;
    #pragma unroll
    for (int off = 16; off > 0; off >>= 1) {
        s  += __shfl_down_sync(0xffffffffu, s, off);
        ss += __shfl_down_sync(0xffffffffu, ss, off);
    }
    if (lane == 0) { sh_s[warp] = s; sh_ss[warp] = ss; }
    __syncthreads();

    if (threadIdx.x == 0) {
        float ts = 0.f, tss = 0.f;
        #pragma unroll
        for (int w = 0; w < 8; w++) { ts += sh_s[w]; tss += sh_ss[w]; }
        g_partial[bid] = make_float2(ts, tss);
        __threadfence();  // publish partial before arriving
        const unsigned old = atomicAdd(&g_ticket[b], 1u);
        if ((old & (CPB - 1)) == CPB - 1) {
            // Last arriver: all 15 siblings have published. Combine in FIXED
            // order (deterministic regardless of arrival order). Nobody waits.
            __threadfence();
            double ds = 0.0, dss = 0.0;
            #pragma unroll
            for (int k = 0; k < CPB; k++) {
                volatile float* p = (volatile float*)&g_partial[b * CPB + k];
                ds  += (double)p[0];
                dss += (double)p[1];
            }
            const double cnt  = (double)CN * (double)zp;
            const double mean = ds / cnt;
            const double var  = (dss - cnt * mean * mean) / (cnt - 1.0);
            const float  stdv = (float)sqrt(var > 0.0 ? var : 0.0);
            g_stats[b] = make_float2((float)mean, 1.0f / (stdv + EPSV));
            __threadfence();
        }
    }
}

// ---------------------------------------------------------------------------
// Kernel B: streaming normalize. 4 float4 per thread, loads front-batched
// (MLP=4); stats fetched once per CTA through shared memory.
// ---------------------------------------------------------------------------
__global__ __launch_bounds__(256) void norm_kernel(
    const float* __restrict__ data, float* __restrict__ out) {
    __shared__ float2 sh_st;
    const size_t base = (size_t)blockIdx.x * NB4;  // float4 index of CTA start
    if (threadIdx.x == 0)
        sh_st = g_stats[blockIdx.x >> 7];  // NB4*128 = 131072 float4 per batch
    __syncthreads();
    const float mean = sh_st.x, rstd = sh_st.y;

    const float4* in4 = reinterpret_cast<const float4*>(data) + base + threadIdx.x;
    float4*       o4  = reinterpret_cast<float4*>(out)        + base + threadIdx.x;

    float4 v0 = in4[0];
    float4 v1 = in4[256];
    float4 v2 = in4[512];
    float4 v3 = in4[768];

    v0.x = (v0.x - mean) * rstd; v0.y = (v0.y - mean) * rstd;
    v0.z = (v0.z - mean) * rstd; v0.w = (v0.w - mean) * rstd;
    v1.x = (v1.x - mean) * rstd; v1.y = (v1.y - mean) * rstd;
    v1.z = (v1.z - mean) * rstd; v1.w = (v1.w - mean) * rstd;
    v2.x = (v2.x - mean) * rstd; v2.y = (v2.y - mean) * rstd;
    v2.z = (v2.z - mean) * rstd; v2.w = (v2.w - mean) * rstd;
    v3.x = (v3.x - mean) * rstd; v3.y = (v3.y - mean) * rstd;
    v3.z = (v3.z - mean) * rstd; v3.w = (v3.w - mean) * rstd;

    o4[0]   = v0;
    o4[256] = v1;
    o4[512] = v2;
    o4[768] = v3;
}

extern "C" void kernel_launch(void* const* d_in, const int* in_sizes, int n_in,
                              void* d_out, int out_size) {
    const float* data     = (const float*)d_in[0];
    const int*   idxes    = (const int*)d_in[1];
    const int*   zero_pos = (const int*)d_in[2];
    float*       out      = (float*)d_out;

    const long long main_elems = (long long)BN * CN * LN;
    const bool has_tail = (long long)out_size > main_elems;
    const unsigned gridA = REDUCE_CTAS + (has_tail ? TAIL_CTAS : 0);

    reduce_stats_tail_kernel<<<gridA, 256>>>(data, idxes, zero_pos, out,
                                             (long long)out_size);
    norm_kernel<<<NORM_CTAS, 256>>>(data, out);
}